// round 1
// baseline (speedup 1.0000x reference)
#include <cuda_runtime.h>
#include <cuda_bf16.h>
#include <cstdint>

#define N_NODES 100000
#define N_EDGES 3200000
#define IN_FEATS 1433
#define HID 16
#define OUT 7

// ---------------- device scratch (static, no runtime alloc) ----------------
__device__ int   g_is64;
__device__ int   g_deg_out[N_NODES];
__device__ int   g_deg_in[N_NODES];
__device__ float g_norm_src[N_NODES];
__device__ float g_norm_dst[N_NODES];
__device__ int   g_src[N_EDGES];
__device__ int   g_dst[N_EDGES];
__device__ __align__(128) float g_x1[N_NODES * 16];
__device__ __align__(128) float g_acc1[N_NODES * 16];
__device__ __align__(128) float g_h[N_NODES * 16];
__device__ __align__(128) float g_x2[N_NODES * 8];
__device__ __align__(128) float g_acc2[N_NODES * 8];

// ---------------- helpers ----------------
__device__ __forceinline__ void red_add_v4(float* addr, float4 v) {
    asm volatile("red.global.add.v4.f32 [%0], {%1, %2, %3, %4};"
                 :: "l"(addr), "f"(v.x), "f"(v.y), "f"(v.z), "f"(v.w)
                 : "memory");
}

// ---------------- kernels ----------------

// Zero accumulators + degree counters.
__global__ void init_kernel() {
    int i = blockIdx.x * blockDim.x + threadIdx.x;
    int stride = gridDim.x * blockDim.x;
    for (int idx = i; idx < N_NODES * 16; idx += stride) {
        g_acc1[idx] = 0.0f;
        if (idx < N_NODES * 8) g_acc2[idx] = 0.0f;
        if (idx < N_NODES) { g_deg_out[idx] = 0; g_deg_in[idx] = 0; }
    }
}

// Detect whether edge_index buffer is int64 or int32 (JAX x64 canonicalization).
__global__ void detect_kernel(const int* ei_words) {
    if (threadIdx.x == 0) {
        int all_zero = 1;
        for (int i = 0; i < 64; i++) {
            if (ei_words[2 * i + 1] != 0) { all_zero = 0; break; }
        }
        g_is64 = all_zero;
    }
}

// Convert edge list to int32 and count degrees.
__global__ void edge_kernel(const void* ei_raw) {
    const long long* ei64 = (const long long*)ei_raw;
    const int*       ei32 = (const int*)ei_raw;
    int is64 = g_is64;
    int e = blockIdx.x * blockDim.x + threadIdx.x;
    if (e >= N_EDGES) return;
    int s, d;
    if (is64) {
        s = (int)ei64[e];
        d = (int)ei64[N_EDGES + e];
    } else {
        s = ei32[e];
        d = ei32[N_EDGES + e];
    }
    g_src[e] = s;
    g_dst[e] = d;
    atomicAdd(&g_deg_out[s], 1);
    atomicAdd(&g_deg_in[d], 1);
}

// norm = rsqrt(max(deg, 1))
__global__ void norm_kernel() {
    int n = blockIdx.x * blockDim.x + threadIdx.x;
    if (n >= N_NODES) return;
    int dout = g_deg_out[n]; if (dout < 1) dout = 1;
    int din  = g_deg_in[n];  if (din  < 1) din  = 1;
    g_norm_src[n] = rsqrtf((float)dout);
    g_norm_dst[n] = rsqrtf((float)din);
}

// GEMM1: x1[n, 0..15] = norm_src[n] * (feat[n, :] @ W1)
// W1 in SMEM; each warp owns 4 nodes; lanes stride over k; warp shuffle reduce.
__global__ void gemm1_kernel(const float* __restrict__ feat,
                             const float* __restrict__ W1) {
    extern __shared__ float sW1[];  // 1433*16 floats
    for (int i = threadIdx.x; i < IN_FEATS * 16; i += blockDim.x)
        sW1[i] = W1[i];
    __syncthreads();

    const int lane = threadIdx.x & 31;
    const int warp_global = (blockIdx.x * blockDim.x + threadIdx.x) >> 5;
    const int nwarps = (gridDim.x * blockDim.x) >> 5;
    const int ngroups = N_NODES / 4;  // 25000

    for (int g = warp_global; g < ngroups; g += nwarps) {
        const int n0 = g * 4;
        const float* __restrict__ f0 = feat + (size_t)n0 * IN_FEATS;

        float acc[4][16];
        #pragma unroll
        for (int j = 0; j < 4; j++)
            #pragma unroll
            for (int c = 0; c < 16; c++)
                acc[j][c] = 0.0f;

        for (int k = lane; k < IN_FEATS; k += 32) {
            const float4 w0 = *(const float4*)&sW1[k * 16 + 0];
            const float4 w1 = *(const float4*)&sW1[k * 16 + 4];
            const float4 w2 = *(const float4*)&sW1[k * 16 + 8];
            const float4 w3 = *(const float4*)&sW1[k * 16 + 12];
            #pragma unroll
            for (int j = 0; j < 4; j++) {
                const float f = __ldg(f0 + (size_t)j * IN_FEATS + k);
                acc[j][0]  += f * w0.x;  acc[j][1]  += f * w0.y;
                acc[j][2]  += f * w0.z;  acc[j][3]  += f * w0.w;
                acc[j][4]  += f * w1.x;  acc[j][5]  += f * w1.y;
                acc[j][6]  += f * w1.z;  acc[j][7]  += f * w1.w;
                acc[j][8]  += f * w2.x;  acc[j][9]  += f * w2.y;
                acc[j][10] += f * w2.z;  acc[j][11] += f * w2.w;
                acc[j][12] += f * w3.x;  acc[j][13] += f * w3.y;
                acc[j][14] += f * w3.z;  acc[j][15] += f * w3.w;
            }
        }

        // Warp-reduce the 64 (node, channel) partials; lane (idx & 31) keeps it.
        float out0 = 0.0f, out1 = 0.0f;
        #pragma unroll
        for (int idx = 0; idx < 64; ++idx) {
            float v = acc[idx >> 4][idx & 15];
            v += __shfl_xor_sync(0xffffffffu, v, 1);
            v += __shfl_xor_sync(0xffffffffu, v, 2);
            v += __shfl_xor_sync(0xffffffffu, v, 4);
            v += __shfl_xor_sync(0xffffffffu, v, 8);
            v += __shfl_xor_sync(0xffffffffu, v, 16);
            if ((idx & 31) == lane) {
                if (idx < 32) out0 = v; else out1 = v;
            }
        }
        {
            const int j0 = lane >> 4, c0 = lane & 15;
            const int n_a = n0 + j0;
            g_x1[(size_t)n_a * 16 + c0] = out0 * g_norm_src[n_a];
            const int idx1 = lane + 32;
            const int j1 = idx1 >> 4, c1 = idx1 & 15;
            const int n_b = n0 + j1;
            g_x1[(size_t)n_b * 16 + c1] = out1 * g_norm_src[n_b];
        }
    }
}

// Scatter layer 1: acc1[dst] += x1[src]  (16 floats per edge, 4x red.v4)
__global__ void scatter1_kernel() {
    int e = blockIdx.x * blockDim.x + threadIdx.x;
    if (e >= N_EDGES) return;
    const int s = g_src[e];
    const int d = g_dst[e];
    const float4* __restrict__ xs = (const float4*)(g_x1 + (size_t)s * 16);
    float4 a = xs[0], b = xs[1], c = xs[2], dd = xs[3];
    float* base = g_acc1 + (size_t)d * 16;
    red_add_v4(base + 0,  a);
    red_add_v4(base + 4,  b);
    red_add_v4(base + 8,  c);
    red_add_v4(base + 12, dd);
}

// h = relu(acc1 * norm_dst + b1)
__global__ void relu_kernel(const float* __restrict__ b1) {
    int i = blockIdx.x * blockDim.x + threadIdx.x;
    if (i >= N_NODES * 16) return;
    const int n = i >> 4;
    const int c = i & 15;
    float v = g_acc1[i] * g_norm_dst[n] + b1[c];
    g_h[i] = v > 0.0f ? v : 0.0f;
}

// GEMM2: x2[n, 0..6] = norm_src[n] * (h[n, :] @ W2), col 7 padded with 0.
__global__ void gemm2_kernel(const float* __restrict__ W2) {
    __shared__ float sW2[HID * OUT];
    for (int i = threadIdx.x; i < HID * OUT; i += blockDim.x) sW2[i] = W2[i];
    __syncthreads();
    int n = blockIdx.x * blockDim.x + threadIdx.x;
    if (n >= N_NODES) return;
    const float4* hp = (const float4*)(g_h + (size_t)n * 16);
    float h[16];
    float4 t;
    t = hp[0]; h[0] = t.x; h[1] = t.y; h[2] = t.z; h[3] = t.w;
    t = hp[1]; h[4] = t.x; h[5] = t.y; h[6] = t.z; h[7] = t.w;
    t = hp[2]; h[8] = t.x; h[9] = t.y; h[10] = t.z; h[11] = t.w;
    t = hp[3]; h[12] = t.x; h[13] = t.y; h[14] = t.z; h[15] = t.w;
    const float ns = g_norm_src[n];
    float* xo = g_x2 + (size_t)n * 8;
    #pragma unroll
    for (int c = 0; c < OUT; c++) {
        float acc = 0.0f;
        #pragma unroll
        for (int k = 0; k < HID; k++) acc += h[k] * sW2[k * OUT + c];
        xo[c] = acc * ns;
    }
    xo[7] = 0.0f;
}

// Scatter layer 2: acc2[dst] += x2[src]  (8 floats per edge, 2x red.v4)
__global__ void scatter2_kernel() {
    int e = blockIdx.x * blockDim.x + threadIdx.x;
    if (e >= N_EDGES) return;
    const int s = g_src[e];
    const int d = g_dst[e];
    const float4* __restrict__ xs = (const float4*)(g_x2 + (size_t)s * 8);
    float4 a = xs[0], b = xs[1];
    float* base = g_acc2 + (size_t)d * 8;
    red_add_v4(base + 0, a);
    red_add_v4(base + 4, b);
}

// out[n, c] = acc2[n, c] * norm_dst[n] + b2[c]
__global__ void final_kernel(const float* __restrict__ b2, float* __restrict__ out) {
    int n = blockIdx.x * blockDim.x + threadIdx.x;
    if (n >= N_NODES) return;
    const float nd = g_norm_dst[n];
    const float* a = g_acc2 + (size_t)n * 8;
    float* o = out + (size_t)n * OUT;
    #pragma unroll
    for (int c = 0; c < OUT; c++) o[c] = a[c] * nd + b2[c];
}

// ---------------- launch ----------------
extern "C" void kernel_launch(void* const* d_in, const int* in_sizes, int n_in,
                              void* d_out, int out_size) {
    const float* feat = (const float*)d_in[0];
    const void*  ei   = d_in[1];
    const float* W1   = (const float*)d_in[2];
    const float* b1   = (const float*)d_in[3];
    const float* W2   = (const float*)d_in[4];
    const float* b2   = (const float*)d_in[5];
    float* out = (float*)d_out;

    const int smem1 = IN_FEATS * 16 * sizeof(float);  // 91712 bytes
    cudaFuncSetAttribute(gemm1_kernel, cudaFuncAttributeMaxDynamicSharedMemorySize, smem1);

    init_kernel<<<(N_NODES * 16 + 255) / 256, 256>>>();
    detect_kernel<<<1, 32>>>((const int*)ei);
    edge_kernel<<<(N_EDGES + 255) / 256, 256>>>(ei);
    norm_kernel<<<(N_NODES + 255) / 256, 256>>>();
    gemm1_kernel<<<296, 256, smem1>>>(feat, W1);
    scatter1_kernel<<<(N_EDGES + 255) / 256, 256>>>();
    relu_kernel<<<(N_NODES * 16 + 255) / 256, 256>>>(b1);
    gemm2_kernel<<<(N_NODES + 255) / 256, 256>>>(W2);
    scatter2_kernel<<<(N_EDGES + 255) / 256, 256>>>();
    final_kernel<<<(N_NODES + 255) / 256, 256>>>(b2, out);
}

// round 4
// speedup vs baseline: 1.5359x; 1.5359x over previous
#include <cuda_runtime.h>
#include <cuda_bf16.h>
#include <cstdint>

#define N_NODES 100000
#define N_EDGES 3200000
#define IN_FEATS 1433
#define HID 16
#define OUT 7
#define NBLK 391  // ceil(100000/256)

// ---------------- device scratch ----------------
__device__ int   g_is64;
__device__ int   g_deg_out[N_NODES];
__device__ int   g_deg_in[N_NODES];
__device__ float g_norm_src[N_NODES];
__device__ float g_norm_dst[N_NODES];
__device__ int   g_src[N_EDGES];
__device__ int   g_dst[N_EDGES];
__device__ int   g_row_start[N_NODES];
__device__ int   g_cursor[N_NODES];
__device__ int   g_csr_src[N_EDGES];
__device__ int   g_part[512];
__device__ __align__(128) float g_x1[N_NODES * 16];
__device__ __align__(128) float g_x2[N_NODES * 8];

// ---------------- helpers ----------------
#define FMA2(d, a, b) asm("fma.rn.f32x2 %0, %1, %2, %3;" : "=l"(d) : "l"(a), "l"(b), "l"(d))

__device__ __forceinline__ unsigned long long pack2(float a, float b) {
    unsigned long long r;
    asm("mov.b64 %0, {%1, %2};" : "=l"(r) : "r"(__float_as_uint(a)), "r"(__float_as_uint(b)));
    return r;
}

// ---------------- kernels ----------------

__global__ void init_kernel() {
    int i = blockIdx.x * blockDim.x + threadIdx.x;
    if (i < N_NODES) { g_deg_out[i] = 0; g_deg_in[i] = 0; }
}

// Detect int64 vs int32 edge buffer (JAX x64 canonicalization).
__global__ void detect_kernel(const int* ei_words) {
    if (threadIdx.x == 0) {
        int all_zero = 1;
        for (int i = 0; i < 64; i++)
            if (ei_words[2 * i + 1] != 0) { all_zero = 0; break; }
        g_is64 = all_zero;
    }
}

// Convert edge list to int32 + degree histograms.
__global__ void edge_kernel(const void* ei_raw) {
    const long long* ei64 = (const long long*)ei_raw;
    const int*       ei32 = (const int*)ei_raw;
    int e = blockIdx.x * blockDim.x + threadIdx.x;
    if (e >= N_EDGES) return;
    int s, d;
    if (g_is64) { s = (int)ei64[e]; d = (int)ei64[N_EDGES + e]; }
    else        { s = ei32[e];      d = ei32[N_EDGES + e]; }
    g_src[e] = s;
    g_dst[e] = d;
    atomicAdd(&g_deg_out[s], 1);
    atomicAdd(&g_deg_in[d], 1);
}

// scan pass 1: per-block sums of deg_in
__global__ void scan1_kernel() {
    __shared__ int s[256];
    int tid = threadIdx.x;
    int i = blockIdx.x * 256 + tid;
    s[tid] = (i < N_NODES) ? g_deg_in[i] : 0;
    __syncthreads();
    for (int off = 128; off > 0; off >>= 1) {
        if (tid < off) s[tid] += s[tid + off];
        __syncthreads();
    }
    if (tid == 0) g_part[blockIdx.x] = s[0];
}

// scan pass 2: exclusive scan of block sums (1 block)
__global__ void scan2_kernel() {
    __shared__ int s[512];
    int tid = threadIdx.x;
    int v = (tid < NBLK) ? g_part[tid] : 0;
    s[tid] = v;
    __syncthreads();
    for (int off = 1; off < 512; off <<= 1) {
        int t = (tid >= off) ? s[tid - off] : 0;
        __syncthreads();
        s[tid] += t;
        __syncthreads();
    }
    g_part[tid] = s[tid] - v;  // exclusive
}

// scan pass 3: per-element row_start + cursor init + norms
__global__ void scan3_kernel() {
    __shared__ int s[256];
    int tid = threadIdx.x;
    int i = blockIdx.x * 256 + tid;
    int v = (i < N_NODES) ? g_deg_in[i] : 0;
    s[tid] = v;
    __syncthreads();
    for (int off = 1; off < 256; off <<= 1) {
        int t = (tid >= off) ? s[tid - off] : 0;
        __syncthreads();
        s[tid] += t;
        __syncthreads();
    }
    if (i < N_NODES) {
        int rs = g_part[blockIdx.x] + s[tid] - v;
        g_row_start[i] = rs;
        g_cursor[i] = rs;
        int dout = g_deg_out[i]; if (dout < 1) dout = 1;
        int din  = g_deg_in[i];  if (din  < 1) din  = 1;
        g_norm_src[i] = rsqrtf((float)dout);
        g_norm_dst[i] = rsqrtf((float)din);
    }
}

// Fill CSR (grouped by dst, storing src ids).
__global__ void fill_kernel() {
    int e = blockIdx.x * blockDim.x + threadIdx.x;
    if (e >= N_EDGES) return;
    int d = g_dst[e];
    int pos = atomicAdd(&g_cursor[d], 1);
    g_csr_src[pos] = g_src[e];
}

// GEMM1: x1[n, :] = norm_src[n] * (feat[n, :] @ W1)
// W1 smem with bank-conflict-free chunk swizzle; f32x2 packed FMA;
// 2 nodes/warp, lanes own consecutive k; butterfly reduce -> 1 store/lane.
__global__ void __launch_bounds__(512) gemm1_kernel(const float* __restrict__ feat,
                                                    const float* __restrict__ W1) {
    extern __shared__ float sW1[];  // 1433*16, swizzled
    for (int i = threadIdx.x; i < IN_FEATS * 16; i += blockDim.x) {
        int k = i >> 4, c = i & 15;
        int r = k + (k >> 2);
        int pp = ((c >> 2) + r) & 3;
        sW1[(k << 4) + (pp << 2) + (c & 3)] = W1[i];
    }
    __syncthreads();

    const int lane = threadIdx.x & 31;
    const int warp_global = (blockIdx.x * blockDim.x + threadIdx.x) >> 5;
    const int nwarps = (gridDim.x * blockDim.x) >> 5;
    const int ngroups = N_NODES / 2;  // 50000

    for (int g = warp_global; g < ngroups; g += nwarps) {
        const int n0 = g * 2;
        const float* __restrict__ f0 = feat + (size_t)n0 * IN_FEATS;

        unsigned long long acc[2][8];
        #pragma unroll
        for (int j = 0; j < 2; j++)
            #pragma unroll
            for (int p = 0; p < 8; p++) acc[j][p] = 0ull;

        #pragma unroll 4
        for (int k = lane; k < IN_FEATS; k += 32) {
            const int kb = k << 4;
            const int r = k + (k >> 2);
            const ulonglong2 u0 = *(const ulonglong2*)&sW1[kb + (((0 + r) & 3) << 2)];
            const ulonglong2 u1 = *(const ulonglong2*)&sW1[kb + (((1 + r) & 3) << 2)];
            const ulonglong2 u2 = *(const ulonglong2*)&sW1[kb + (((2 + r) & 3) << 2)];
            const ulonglong2 u3 = *(const ulonglong2*)&sW1[kb + (((3 + r) & 3) << 2)];
            #pragma unroll
            for (int j = 0; j < 2; j++) {
                const float f = __ldg(f0 + (size_t)j * IN_FEATS + k);
                const unsigned long long ff = pack2(f, f);
                FMA2(acc[j][0], u0.x, ff);
                FMA2(acc[j][1], u0.y, ff);
                FMA2(acc[j][2], u1.x, ff);
                FMA2(acc[j][3], u1.y, ff);
                FMA2(acc[j][4], u2.x, ff);
                FMA2(acc[j][5], u2.y, ff);
                FMA2(acc[j][6], u3.x, ff);
                FMA2(acc[j][7], u3.y, ff);
            }
        }

        // unpack to 32 scalars (value idx = j*16 + c)
        float vals[32];
        #pragma unroll
        for (int j = 0; j < 2; j++)
            #pragma unroll
            for (int p = 0; p < 8; p++) {
                unsigned lo, hi;
                asm("mov.b64 {%0, %1}, %2;" : "=r"(lo), "=r"(hi) : "l"(acc[j][p]));
                vals[j * 16 + p * 2]     = __uint_as_float(lo);
                vals[j * 16 + p * 2 + 1] = __uint_as_float(hi);
            }

        float outv = 0.0f;
        #pragma unroll
        for (int idx = 0; idx < 32; idx++) {
            float v = vals[idx];
            v += __shfl_xor_sync(0xffffffffu, v, 1);
            v += __shfl_xor_sync(0xffffffffu, v, 2);
            v += __shfl_xor_sync(0xffffffffu, v, 4);
            v += __shfl_xor_sync(0xffffffffu, v, 8);
            v += __shfl_xor_sync(0xffffffffu, v, 16);
            if (idx == lane) outv = v;
        }
        const int n = n0 + (lane >> 4);
        g_x1[(size_t)n * 16 + (lane & 15)] = outv * g_norm_src[n];
    }
}

// Gather layer 1 (CSR, no atomics) fused with relu + bias + GEMM2 epilogue.
// One warp per dst node. lanes: c = lane&15 (channel), half = lane>>4 (edge parity).
__global__ void gather1_kernel(const float* __restrict__ b1,
                               const float* __restrict__ W2) {
    __shared__ float sW2[16 * 8];  // [k][c2], c2 7 used, col 7 zero-padded
    __shared__ float sb1[16];
    for (int i = threadIdx.x; i < 16 * 8; i += blockDim.x) {
        int k = i >> 3, c2 = i & 7;
        sW2[i] = (c2 < OUT) ? W2[k * OUT + c2] : 0.0f;
    }
    if (threadIdx.x < 16) sb1[threadIdx.x] = b1[threadIdx.x];
    __syncthreads();

    const int n = (blockIdx.x * blockDim.x + threadIdx.x) >> 5;
    if (n >= N_NODES) return;
    const int lane = threadIdx.x & 31;
    const int c = lane & 15;
    const int half = lane >> 4;

    const int start = g_row_start[n];
    const int end = start + g_deg_in[n];

    float acc = 0.0f;
    for (int e = start + half; e < end; e += 2) {
        const int s = g_csr_src[e];
        acc += g_x1[(size_t)s * 16 + c];
    }
    acc += __shfl_xor_sync(0xffffffffu, acc, 16);  // all lanes now hold channel-c sum

    const float nd = g_norm_dst[n];
    const float h = fmaxf(acc * nd + sb1[c], 0.0f);  // valid on all lanes (c dup in halves)

    // GEMM2 in-warp: x2[c2] = norm_src * sum_k h[k] * W2[k][c2]
    float acc2 = 0.0f;
    const int c2 = lane & 7;
    #pragma unroll
    for (int k = 0; k < 16; k++) {
        const float hk = __shfl_sync(0xffffffffu, h, k);  // lane k holds channel k
        acc2 += hk * sW2[k * 8 + c2];
    }
    if (lane < 8) {
        const float ns = g_norm_src[n];
        g_x2[(size_t)n * 8 + lane] = (lane < OUT) ? acc2 * ns : 0.0f;
    }
}

// Gather layer 2 fused with final bias. One warp per dst node.
// lanes: c = lane&7, quarter = lane>>3.
__global__ void gather2_kernel(const float* __restrict__ b2,
                               float* __restrict__ out) {
    __shared__ float sb2[8];
    if (threadIdx.x < 8) sb2[threadIdx.x] = (threadIdx.x < OUT) ? b2[threadIdx.x] : 0.0f;
    __syncthreads();

    const int n = (blockIdx.x * blockDim.x + threadIdx.x) >> 5;
    if (n >= N_NODES) return;
    const int lane = threadIdx.x & 31;
    const int c = lane & 7;
    const int quarter = lane >> 3;

    const int start = g_row_start[n];
    const int end = start + g_deg_in[n];

    float acc = 0.0f;
    for (int e = start + quarter; e < end; e += 4) {
        const int s = g_csr_src[e];
        acc += g_x2[(size_t)s * 8 + c];
    }
    acc += __shfl_xor_sync(0xffffffffu, acc, 8);
    acc += __shfl_xor_sync(0xffffffffu, acc, 16);

    if (lane < OUT) {
        out[(size_t)n * OUT + lane] = acc * g_norm_dst[n] + sb2[lane];
    }
}

// ---------------- launch ----------------
extern "C" void kernel_launch(void* const* d_in, const int* in_sizes, int n_in,
                              void* d_out, int out_size) {
    const float* feat = (const float*)d_in[0];
    const void*  ei   = d_in[1];
    const float* W1   = (const float*)d_in[2];
    const float* b1   = (const float*)d_in[3];
    const float* W2   = (const float*)d_in[4];
    const float* b2   = (const float*)d_in[5];
    float* out = (float*)d_out;

    const int smem1 = IN_FEATS * 16 * sizeof(float);  // 91712 bytes
    cudaFuncSetAttribute(gemm1_kernel, cudaFuncAttributeMaxDynamicSharedMemorySize, smem1);

    init_kernel<<<NBLK, 256>>>();
    detect_kernel<<<1, 32>>>((const int*)ei);
    edge_kernel<<<(N_EDGES + 255) / 256, 256>>>(ei);
    scan1_kernel<<<NBLK, 256>>>();
    scan2_kernel<<<1, 512>>>();
    scan3_kernel<<<NBLK, 256>>>();
    fill_kernel<<<(N_EDGES + 255) / 256, 256>>>();
    gemm1_kernel<<<148, 512, smem1>>>(feat, W1);
    gather1_kernel<<<(N_NODES * 32 + 255) / 256, 256>>>(b1, W2);
    gather2_kernel<<<(N_NODES * 32 + 255) / 256, 256>>>(b2, out);
}

// round 9
// speedup vs baseline: 2.3293x; 1.5166x over previous
#include <cuda_runtime.h>
#include <cuda_bf16.h>
#include <cstdint>

#define N_NODES 100000
#define N_EDGES 3200000
#define IN_FEATS 1433
#define HID 16
#define OUT 7
#define NBLK 391  // ceil(100000/256)

// ---------------- device scratch ----------------
__device__ int   g_is64;
__device__ int   g_deg_out[N_NODES];
__device__ int   g_deg_in[N_NODES];
__device__ float g_norm_src[N_NODES];
__device__ float g_norm_dst[N_NODES];
__device__ int   g_row_start[N_NODES];
__device__ int   g_cursor[N_NODES];
__device__ int   g_csr_src[N_EDGES];
__device__ int   g_part[512];
__device__ __align__(128) float g_x1[N_NODES * 16];
__device__ __align__(128) float g_x2[N_NODES * 8];

// ---------------- helpers ----------------
#define FMA2(d, a, b) asm("fma.rn.f32x2 %0, %1, %2, %3;" : "=l"(d) : "l"(a), "l"(b), "l"(d))
#define ADD2(d, a, b) asm("add.rn.f32x2 %0, %1, %2;" : "=l"(d) : "l"(a), "l"(b))

__device__ __forceinline__ unsigned long long pack2(float a, float b) {
    unsigned long long r;
    asm("mov.b64 %0, {%1, %2};" : "=l"(r) : "r"(__float_as_uint(a)), "r"(__float_as_uint(b)));
    return r;
}

// ---------------- kernels ----------------

// Zero degree counters + detect int64 vs int32 edge buffer.
__global__ void init_kernel(const int* ei_words) {
    int i = blockIdx.x * blockDim.x + threadIdx.x;
    if (i < N_NODES) { g_deg_out[i] = 0; g_deg_in[i] = 0; }
    if (i == 0) {
        int all_zero = 1;
        for (int t = 0; t < 64; t++)
            if (ei_words[2 * t + 1] != 0) { all_zero = 0; break; }
        g_is64 = all_zero;
    }
}

// Degree histograms (no edge copy — fill re-reads the L2-resident edge list).
__global__ void edge_kernel(const void* ei_raw) {
    int e = blockIdx.x * blockDim.x + threadIdx.x;
    if (e >= N_EDGES) return;
    int s, d;
    if (g_is64) {
        s = (int)((const long long*)ei_raw)[e];
        d = (int)((const long long*)ei_raw)[N_EDGES + e];
    } else {
        s = ((const int*)ei_raw)[e];
        d = ((const int*)ei_raw)[N_EDGES + e];
    }
    atomicAdd(&g_deg_out[s], 1);
    atomicAdd(&g_deg_in[d], 1);
}

// scan pass 1: per-block sums of deg_in
__global__ void scan1_kernel() {
    __shared__ int s[256];
    int tid = threadIdx.x;
    int i = blockIdx.x * 256 + tid;
    s[tid] = (i < N_NODES) ? g_deg_in[i] : 0;
    __syncthreads();
    for (int off = 128; off > 0; off >>= 1) {
        if (tid < off) s[tid] += s[tid + off];
        __syncthreads();
    }
    if (tid == 0) g_part[blockIdx.x] = s[0];
}

// scan pass 2: exclusive scan of block sums (1 block)
__global__ void scan2_kernel() {
    __shared__ int s[512];
    int tid = threadIdx.x;
    int v = (tid < NBLK) ? g_part[tid] : 0;
    s[tid] = v;
    __syncthreads();
    for (int off = 1; off < 512; off <<= 1) {
        int t = (tid >= off) ? s[tid - off] : 0;
        __syncthreads();
        s[tid] += t;
        __syncthreads();
    }
    g_part[tid] = s[tid] - v;  // exclusive
}

// scan pass 3: per-element row_start + cursor init + norms
__global__ void scan3_kernel() {
    __shared__ int s[256];
    int tid = threadIdx.x;
    int i = blockIdx.x * 256 + tid;
    int v = (i < N_NODES) ? g_deg_in[i] : 0;
    s[tid] = v;
    __syncthreads();
    for (int off = 1; off < 256; off <<= 1) {
        int t = (tid >= off) ? s[tid - off] : 0;
        __syncthreads();
        s[tid] += t;
        __syncthreads();
    }
    if (i < N_NODES) {
        int rs = g_part[blockIdx.x] + s[tid] - v;
        g_row_start[i] = rs;
        g_cursor[i] = rs;
        int dout = g_deg_out[i]; if (dout < 1) dout = 1;
        int din  = g_deg_in[i];  if (din  < 1) din  = 1;
        g_norm_src[i] = rsqrtf((float)dout);
        g_norm_dst[i] = rsqrtf((float)din);
    }
}

// Fill CSR (grouped by dst, storing src ids) straight from the edge list.
__global__ void fill_kernel(const void* ei_raw) {
    int e = blockIdx.x * blockDim.x + threadIdx.x;
    if (e >= N_EDGES) return;
    int s, d;
    if (g_is64) {
        s = (int)((const long long*)ei_raw)[e];
        d = (int)((const long long*)ei_raw)[N_EDGES + e];
    } else {
        s = ((const int*)ei_raw)[e];
        d = ((const int*)ei_raw)[N_EDGES + e];
    }
    int pos = atomicAdd(&g_cursor[d], 1);
    g_csr_src[pos] = s;
}

// GEMM1: x1[n, :] = norm_src[n] * (feat[n, :] @ W1)
// 4 nodes/warp (halves smem W traffic vs 2), swizzled conflict-free W1 in smem,
// f32x2 FMA, feat prefetch for MLP, merged transpose-reduce (62 SHFL/job).
__global__ void __launch_bounds__(512) gemm1_kernel(const float* __restrict__ feat,
                                                    const float* __restrict__ W1) {
    extern __shared__ float sW1[];  // 1433*16, swizzled
    for (int i = threadIdx.x; i < IN_FEATS * 16; i += blockDim.x) {
        int k = i >> 4, c = i & 15;
        int r = k + (k >> 2);
        int pp = ((c >> 2) + r) & 3;
        sW1[(k << 4) + (pp << 2) + (c & 3)] = W1[i];
    }
    __syncthreads();

    const int lane = threadIdx.x & 31;
    const int rv = __brev(lane) >> 27;  // bit-reversed lane = final value index
    const int warp_global = blockIdx.x * (blockDim.x >> 5) + (threadIdx.x >> 5);
    const int nwarps = gridDim.x * (blockDim.x >> 5);

    for (int g = warp_global; g < N_NODES / 4; g += nwarps) {
        const int n0 = g * 4;
        const float* __restrict__ f0 = feat + (size_t)n0 * IN_FEATS;

        // v[j*8+p] = f32x2 partial for node j, channels (2p, 2p+1)
        unsigned long long v[32];
        #pragma unroll
        for (int i = 0; i < 32; i++) v[i] = 0ull;

        float fcur[4];
        #pragma unroll
        for (int j = 0; j < 4; j++)
            fcur[j] = __ldg(f0 + (size_t)j * IN_FEATS + lane);

        for (int k = lane; k < IN_FEATS; k += 32) {
            const int kb = k << 4;
            const int r = k + (k >> 2);
            const ulonglong2 u0 = *(const ulonglong2*)&sW1[kb + (((0 + r) & 3) << 2)];
            const ulonglong2 u1 = *(const ulonglong2*)&sW1[kb + (((1 + r) & 3) << 2)];
            const ulonglong2 u2 = *(const ulonglong2*)&sW1[kb + (((2 + r) & 3) << 2)];
            const ulonglong2 u3 = *(const ulonglong2*)&sW1[kb + (((3 + r) & 3) << 2)];

            float fnext[4] = {0.f, 0.f, 0.f, 0.f};
            const int k2 = k + 32;
            if (k2 < IN_FEATS) {
                #pragma unroll
                for (int j = 0; j < 4; j++)
                    fnext[j] = __ldg(f0 + (size_t)j * IN_FEATS + k2);
            }

            #pragma unroll
            for (int j = 0; j < 4; j++) {
                const unsigned long long ff = pack2(fcur[j], fcur[j]);
                FMA2(v[j * 8 + 0], u0.x, ff);
                FMA2(v[j * 8 + 1], u0.y, ff);
                FMA2(v[j * 8 + 2], u1.x, ff);
                FMA2(v[j * 8 + 3], u1.y, ff);
                FMA2(v[j * 8 + 4], u2.x, ff);
                FMA2(v[j * 8 + 5], u2.y, ff);
                FMA2(v[j * 8 + 6], u3.x, ff);
                FMA2(v[j * 8 + 7], u3.y, ff);
            }
            #pragma unroll
            for (int j = 0; j < 4; j++) fcur[j] = fnext[j];
        }

        // Merged transpose-reduce: each round exchanges only the relinquished
        // half; value count halves per round. Lane ends holding index bitrev(lane).
        #pragma unroll
        for (int round = 0; round < 5; round++) {
            const int m = 1 << round;
            const int h = 16 >> round;
            const bool up = (lane & m) != 0;
            #pragma unroll
            for (int i = 0; i < h; i++) {
                unsigned long long send, keep;
                if (up) { send = v[i];     keep = v[i + h]; }
                else    { send = v[i + h]; keep = v[i]; }
                unsigned long long recv = __shfl_xor_sync(0xffffffffu, send, m);
                ADD2(v[i], keep, recv);
            }
        }

        const int n = n0 + (rv >> 3);
        const int c0 = (rv & 7) << 1;
        unsigned lo, hi;
        asm("mov.b64 {%0, %1}, %2;" : "=r"(lo), "=r"(hi) : "l"(v[0]));
        const float ns = g_norm_src[n];
        float2 o;
        o.x = __uint_as_float(lo) * ns;
        o.y = __uint_as_float(hi) * ns;
        *(float2*)&g_x1[(size_t)n * 16 + c0] = o;
    }
}

// Gather layer 1 (CSR, no atomics) fused with relu + bias + GEMM2 epilogue.
// One warp per dst node. lanes: c = lane&15 (channel), half = lane>>4 (edge parity).
__global__ void gather1_kernel(const float* __restrict__ b1,
                               const float* __restrict__ W2) {
    __shared__ float sW2[16 * 8];  // [k][c2], c2 7 used, col 7 zero-padded
    __shared__ float sb1[16];
    for (int i = threadIdx.x; i < 16 * 8; i += blockDim.x) {
        int k = i >> 3, c2 = i & 7;
        sW2[i] = (c2 < OUT) ? W2[k * OUT + c2] : 0.0f;
    }
    if (threadIdx.x < 16) sb1[threadIdx.x] = b1[threadIdx.x];
    __syncthreads();

    const int n = (blockIdx.x * blockDim.x + threadIdx.x) >> 5;
    if (n >= N_NODES) return;
    const int lane = threadIdx.x & 31;
    const int c = lane & 15;
    const int half = lane >> 4;

    const int start = g_row_start[n];
    const int end = start + g_deg_in[n];

    float acc = 0.0f;
    for (int e = start + half; e < end; e += 2) {
        const int s = g_csr_src[e];
        acc += g_x1[(size_t)s * 16 + c];
    }
    acc += __shfl_xor_sync(0xffffffffu, acc, 16);  // all lanes hold channel-c sum

    const float nd = g_norm_dst[n];
    const float h = fmaxf(acc * nd + sb1[c], 0.0f);

    // GEMM2 in-warp: x2[c2] = norm_src * sum_k h[k] * W2[k][c2]
    float acc2 = 0.0f;
    const int c2 = lane & 7;
    #pragma unroll
    for (int k = 0; k < 16; k++) {
        const float hk = __shfl_sync(0xffffffffu, h, k);  // lane k holds channel k
        acc2 += hk * sW2[k * 8 + c2];
    }
    if (lane < 8) {
        const float ns = g_norm_src[n];
        g_x2[(size_t)n * 8 + lane] = (lane < OUT) ? acc2 * ns : 0.0f;
    }
}

// Gather layer 2 fused with final bias. One warp per dst node.
__global__ void gather2_kernel(const float* __restrict__ b2,
                               float* __restrict__ out) {
    __shared__ float sb2[8];
    if (threadIdx.x < 8) sb2[threadIdx.x] = (threadIdx.x < OUT) ? b2[threadIdx.x] : 0.0f;
    __syncthreads();

    const int n = (blockIdx.x * blockDim.x + threadIdx.x) >> 5;
    if (n >= N_NODES) return;
    const int lane = threadIdx.x & 31;
    const int c = lane & 7;
    const int quarter = lane >> 3;

    const int start = g_row_start[n];
    const int end = start + g_deg_in[n];

    float acc = 0.0f;
    for (int e = start + quarter; e < end; e += 4) {
        const int s = g_csr_src[e];
        acc += g_x2[(size_t)s * 8 + c];
    }
    acc += __shfl_xor_sync(0xffffffffu, acc, 8);
    acc += __shfl_xor_sync(0xffffffffu, acc, 16);

    if (lane < OUT) {
        out[(size_t)n * OUT + lane] = acc * g_norm_dst[n] + sb2[lane];
    }
}

// ---------------- launch ----------------
extern "C" void kernel_launch(void* const* d_in, const int* in_sizes, int n_in,
                              void* d_out, int out_size) {
    const float* feat = (const float*)d_in[0];
    const void*  ei   = d_in[1];
    const float* W1   = (const float*)d_in[2];
    const float* b1   = (const float*)d_in[3];
    const float* W2   = (const float*)d_in[4];
    const float* b2   = (const float*)d_in[5];
    float* out = (float*)d_out;

    const int smem1 = IN_FEATS * 16 * sizeof(float);  // 91712 bytes
    cudaFuncSetAttribute(gemm1_kernel, cudaFuncAttributeMaxDynamicSharedMemorySize, smem1);

    init_kernel<<<NBLK, 256>>>((const int*)ei);
    edge_kernel<<<(N_EDGES + 255) / 256, 256>>>(ei);
    scan1_kernel<<<NBLK, 256>>>();
    scan2_kernel<<<1, 512>>>();
    scan3_kernel<<<NBLK, 256>>>();
    fill_kernel<<<(N_EDGES + 255) / 256, 256>>>(ei);
    gemm1_kernel<<<148, 512, smem1>>>(feat, W1);
    gather1_kernel<<<(N_NODES * 32 + 255) / 256, 256>>>(b1, W2);
    gather2_kernel<<<(N_NODES * 32 + 255) / 256, 256>>>(b2, out);
}